// round 1
// baseline (speedup 1.0000x reference)
#include <cuda_runtime.h>
#include <math.h>

#define N_VOX (256*256*256)        // 16777216 voxels per volume
#define NUM_SHELLS 222             // floor(sqrt(3)*128) + 1
#define NB (2*3*NUM_SHELLS)        // 2 batches x {num,px,py} x shells = 1332

// Scratch: 4 complex volumes [X_b0, X_b1, Y_b0, Y_b1], 512 MiB total.
__device__ float2 g_F[(size_t)4 * N_VOX];
__device__ float  g_acc[NB];
__device__ float2 g_tw[128];       // W_256^k = exp(-2*pi*i*k/256), k<128

__device__ __forceinline__ float2 cmulf(float2 a, float2 b) {
    return make_float2(a.x*b.x - a.y*b.y, a.x*b.y + a.y*b.x);
}

// ---------------------------------------------------------------------------
// Init: zero accumulators, build twiddle table. Runs every launch (deterministic).
// ---------------------------------------------------------------------------
__global__ void init_kernel() {
    int t = threadIdx.x;
    for (int i = t; i < NB; i += blockDim.x) g_acc[i] = 0.0f;
    for (int k = t; k < 128; k += blockDim.x) {
        float ang = -6.283185307179586f * (float)k / 256.0f;
        float s, c;
        sincosf(ang, &s, &c);
        g_tw[k] = make_float2(c, s);
    }
}

// ---------------------------------------------------------------------------
// Pass 1: FFT along x (contiguous). Real input -> complex scratch.
// 2 lines per block of 256 threads; 128 butterfly-threads per line.
// ---------------------------------------------------------------------------
__global__ void fft_x_kernel(const float* __restrict__ X, const float* __restrict__ Y) {
    __shared__ float2 sh[2][256];
    __shared__ float2 tw[128];
    int tid = threadIdx.x;
    if (tid < 128) tw[tid] = g_tw[tid];

    int l   = tid >> 7;          // line within block (0/1)
    int j   = tid & 127;         // butterfly index
    int line = blockIdx.x * 2 + l;        // 0 .. 262143
    int vol  = line >> 16;                // 65536 lines per volume
    int lin  = line & 65535;
    const float* src = (vol < 2) ? (X + (size_t)vol * N_VOX)
                                 : (Y + (size_t)(vol - 2) * N_VOX);
    size_t base = (size_t)lin * 256;

    // coalesced load + bit-reversed scatter into shared
    float v0 = src[base + j];
    float v1 = src[base + j + 128];
    sh[l][__brev((unsigned)j) >> 24]         = make_float2(v0, 0.0f);
    sh[l][__brev((unsigned)(j + 128)) >> 24] = make_float2(v1, 0.0f);
    __syncthreads();

#pragma unroll
    for (int st = 0; st < 8; st++) {
        int half = 1 << st;
        int pos  = j & (half - 1);
        int i0   = ((j >> st) << (st + 1)) + pos;
        int i1   = i0 + half;
        float2 w = tw[pos << (7 - st)];
        float2 a = sh[l][i0];
        float2 b = cmulf(w, sh[l][i1]);
        sh[l][i0] = make_float2(a.x + b.x, a.y + b.y);
        sh[l][i1] = make_float2(a.x - b.x, a.y - b.y);
        __syncthreads();
    }

    float2* dst = g_F + (size_t)vol * N_VOX + base;
    dst[j]       = sh[l][j];
    dst[j + 128] = sh[l][j + 128];
}

// ---------------------------------------------------------------------------
// Passes 2/3: FFT along a strided axis. Block handles a tile of 16 adjacent
// x-columns over the full 256-point line, staged through shared memory so
// global loads/stores are 128B-coalesced.
//   pass 2 (y): line_stride = 256,   outer_stride = 65536 (outer = z)
//   pass 3 (z): line_stride = 65536, outer_stride = 256   (outer = y)
// Grid: 4 vols * 256 outer * 16 tiles = 16384 blocks of 256 threads.
// ---------------------------------------------------------------------------
__global__ void fft_strided_kernel(int line_stride, int outer_stride) {
    __shared__ float2 sh[256][17];   // +1 pad to break stride conflicts
    __shared__ float2 tw[128];
    int tid = threadIdx.x;
    if (tid < 128) tw[tid] = g_tw[tid];

    int b    = blockIdx.x;
    int vol  = b >> 12;              // 4096 blocks per volume
    int rem  = b & 4095;
    int outer = rem >> 4;
    int tile  = rem & 15;
    float2* data = g_F + (size_t)vol * N_VOX
                       + (size_t)outer * (size_t)outer_stride
                       + (size_t)tile * 16;

    int c  = tid & 15;               // column within tile
    int l0 = tid >> 4;               // 0..15

    // coalesced load, bit-reversed row scatter
#pragma unroll
    for (int it = 0; it < 16; it++) {
        int ll = l0 + (it << 4);
        sh[__brev((unsigned)ll) >> 24][c] = data[(size_t)ll * line_stride + c];
    }
    __syncthreads();

#pragma unroll
    for (int st = 0; st < 8; st++) {
        int half = 1 << st;
#pragma unroll
        for (int k = 0; k < 8; k++) {
            int j   = l0 + (k << 4);            // 0..127, distinct per (thread,k)
            int pos = j & (half - 1);
            int i0  = ((j >> st) << (st + 1)) + pos;
            int i1  = i0 + half;
            float2 w  = tw[pos << (7 - st)];
            float2 a  = sh[i0][c];
            float2 bb = cmulf(w, sh[i1][c]);
            sh[i0][c] = make_float2(a.x + bb.x, a.y + bb.y);
            sh[i1][c] = make_float2(a.x - bb.x, a.y - bb.y);
        }
        __syncthreads();
    }

#pragma unroll
    for (int it = 0; it < 16; it++) {
        int ll = l0 + (it << 4);
        data[(size_t)ll * line_stride + c] = sh[ll][c];
    }
}

// ---------------------------------------------------------------------------
// Shell reduction: per-voxel bin + shared-privatized accumulation of
// {num, px, py} for both batches, then global atomic flush.
// ---------------------------------------------------------------------------
__global__ void reduce_kernel() {
    __shared__ float sh[NB];
    int tid = threadIdx.x;
    for (int i = tid; i < NB; i += 256) sh[i] = 0.0f;
    __syncthreads();

    unsigned stride = gridDim.x * 256u;
    for (unsigned idx = blockIdx.x * 256u + tid; idx < (unsigned)N_VOX; idx += stride) {
        int z = idx >> 16, y = (idx >> 8) & 255, x = idx & 255;
        int fz = (z < 128) ? z : z - 256;
        int fy = (y < 128) ? y : y - 256;
        int fx = (x < 128) ? x : x - 256;
        int r2 = fz*fz + fy*fy + fx*fx;
        int bin = (int)sqrtf((float)r2);   // floor(sqrt) for integer r2 (exact: sqrtf IEEE-rounded)

        float2 a0 = g_F[idx];
        float2 a1 = g_F[(size_t)N_VOX + idx];
        float2 b0 = g_F[(size_t)2*N_VOX + idx];
        float2 b1 = g_F[(size_t)3*N_VOX + idx];

        atomicAdd(&sh[bin],                   a0.x*b0.x + a0.y*b0.y);
        atomicAdd(&sh[NUM_SHELLS   + bin],    a0.x*a0.x + a0.y*a0.y);
        atomicAdd(&sh[2*NUM_SHELLS + bin],    b0.x*b0.x + b0.y*b0.y);
        atomicAdd(&sh[3*NUM_SHELLS + bin],    a1.x*b1.x + a1.y*b1.y);
        atomicAdd(&sh[4*NUM_SHELLS + bin],    a1.x*a1.x + a1.y*a1.y);
        atomicAdd(&sh[5*NUM_SHELLS + bin],    b1.x*b1.x + b1.y*b1.y);
    }
    __syncthreads();
    for (int i = tid; i < NB; i += 256) atomicAdd(&g_acc[i], sh[i]);
}

// ---------------------------------------------------------------------------
// Final: fsc = num / sqrt(px*py + 1e-8), mean over 2 batches x 222 shells.
// ---------------------------------------------------------------------------
__global__ void final_kernel(float* __restrict__ out) {
    __shared__ float red[256];
    int tid = threadIdx.x;
    float s = 0.0f;
    for (int i = tid; i < 2 * NUM_SHELLS; i += 256) {
        int bt = i / NUM_SHELLS;
        int sh_ = i % NUM_SHELLS;
        const float* acc = g_acc + bt * 3 * NUM_SHELLS;
        float num = acc[sh_];
        float px  = acc[NUM_SHELLS + sh_];
        float py  = acc[2*NUM_SHELLS + sh_];
        s += num / sqrtf(px * py + 1e-8f);
    }
    red[tid] = s;
    __syncthreads();
    for (int o = 128; o > 0; o >>= 1) {
        if (tid < o) red[tid] += red[tid + o];
        __syncthreads();
    }
    if (tid == 0) out[0] = red[0] / (2.0f * NUM_SHELLS);
}

// ---------------------------------------------------------------------------
extern "C" void kernel_launch(void* const* d_in, const int* in_sizes, int n_in,
                              void* d_out, int out_size) {
    const float* X = (const float*)d_in[0];
    const float* Y = (const float*)d_in[1];

    init_kernel<<<1, 256>>>();
    fft_x_kernel<<<131072, 256>>>(X, Y);          // 4 vols * 65536 lines / 2
    fft_strided_kernel<<<16384, 256>>>(256, 65536);   // y-FFT
    fft_strided_kernel<<<16384, 256>>>(65536, 256);   // z-FFT
    reduce_kernel<<<1024, 256>>>();
    final_kernel<<<1, 256>>>((float*)d_out);
}

// round 4
// speedup vs baseline: 1.7182x; 1.7182x over previous
#include <cuda_runtime.h>
#include <math.h>

#define N_VOX (256*256*256)
#define NUM_SHELLS 222
#define NB (2*3*NUM_SHELLS)

// Scratch: 4 complex volumes [X_b0, X_b1, Y_b0, Y_b1], 512 MiB.
__device__ float2 g_F[(size_t)4 * N_VOX];
__device__ float  g_acc[NB];
__device__ float2 g_tw[256];   // W256^k

__constant__ float2 TW16C[8] = {
    { 1.0f,           0.0f          },
    { 0.92387953251f, -0.38268343236f },
    { 0.70710678119f, -0.70710678119f },
    { 0.38268343236f, -0.92387953251f },
    { 0.0f,          -1.0f          },
    {-0.38268343236f, -0.92387953251f },
    {-0.70710678119f, -0.70710678119f },
    {-0.92387953251f, -0.38268343236f }
};

__device__ __forceinline__ float2 cmulf(float2 a, float2 b) {
    return make_float2(a.x*b.x - a.y*b.y, a.x*b.y + a.y*b.x);
}

// 16-point radix-2 DIT FFT, fully in registers. Natural in -> natural out.
__device__ __forceinline__ void fft16(float2 v[16]) {
    // bit-reverse (4-bit)
    float2 t;
#define SWP(a,b) { t = v[a]; v[a] = v[b]; v[b] = t; }
    SWP(1,8) SWP(2,4) SWP(3,12) SWP(5,10) SWP(7,14) SWP(11,13)
#undef SWP
#pragma unroll
    for (int st = 0; st < 4; st++) {
        int half = 1 << st;
#pragma unroll
        for (int j = 0; j < 8; j++) {
            int pos = j & (half - 1);
            int i0  = ((j >> st) << (st + 1)) + pos;
            int i1  = i0 + half;
            float2 w = TW16C[pos << (3 - st)];
            float2 b = cmulf(w, v[i1]);
            float2 a = v[i0];
            v[i0] = make_float2(a.x + b.x, a.y + b.y);
            v[i1] = make_float2(a.x - b.x, a.y - b.y);
        }
    }
}

// ---------------------------------------------------------------------------
__global__ void init_kernel() {
    int tid = threadIdx.x;
    for (int i = tid; i < NB; i += blockDim.x) g_acc[i] = 0.0f;
    if (tid < 256) {
        float ang = -6.283185307179586f * (float)tid / 256.0f;
        float s, c;
        sincosf(ang, &s, &c);
        g_tw[tid] = make_float2(c, s);
    }
}

// ---------------------------------------------------------------------------
// Pass 1: x-FFT (contiguous), real -> complex. 16 lines/block, 16 thr/line.
// 256-pt FFT = 16pt(reg) -> twiddle -> shared transpose -> 16pt(reg).
// ---------------------------------------------------------------------------
__global__ void __launch_bounds__(256)
fft_x_kernel(const float* __restrict__ X, const float* __restrict__ Y) {
    __shared__ float2 sh[16][16][17];   // [line][n1][k2], pad 17 -> conflict-free
    __shared__ float2 tws[256];
    int tid = threadIdx.x;
    tws[tid] = g_tw[tid];
    int tt = tid & 15;          // n1 / k2 role
    int l  = tid >> 4;          // line in block
    int line = blockIdx.x * 16 + l;
    int vol  = line >> 16;
    int lin  = line & 65535;
    const float* src = (vol < 2) ? (X + (size_t)vol * N_VOX)
                                 : (Y + (size_t)(vol - 2) * N_VOX);
    size_t base = (size_t)lin * 256;

    float2 v[16];
#pragma unroll
    for (int i = 0; i < 16; i++)
        v[i] = make_float2(src[base + tt + 16*i], 0.0f);
    fft16(v);                       // v[k2] over n2, fixed n1=tt
    __syncthreads();                // tws ready (also covers first iteration)
#pragma unroll
    for (int k2 = 1; k2 < 16; k2++)
        v[k2] = cmulf(v[k2], tws[tt * k2]);
#pragma unroll
    for (int k2 = 0; k2 < 16; k2++)
        sh[l][tt][k2] = v[k2];
    __syncthreads();
    float2 u[16];
#pragma unroll
    for (int n1 = 0; n1 < 16; n1++)
        u[n1] = sh[l][n1][tt];      // fixed k2 = tt
    fft16(u);                       // u[k1] = F[tt + 16*k1]
    float2* dst = g_F + (size_t)vol * N_VOX + base;
#pragma unroll
    for (int k1 = 0; k1 < 16; k1++)
        dst[tt + 16*k1] = u[k1];
}

// ---------------------------------------------------------------------------
// Pass 2: y-FFT, in-place, stride 256. Block = (vol, z, x-tile of 16).
// Direct strided global<->register, one shared transpose.
// ---------------------------------------------------------------------------
__global__ void __launch_bounds__(256)
fft_y_kernel() {
    __shared__ float2 sh[16][16][16];   // [n1][k2][c] -> conflict-free
    __shared__ float2 tws[256];
    int tid = threadIdx.x;
    tws[tid] = g_tw[tid];
    int c = tid & 15;
    int t = tid >> 4;
    int b    = blockIdx.x;
    int vol  = b >> 12;
    int rem  = b & 4095;
    int z    = rem >> 4;
    int tile = rem & 15;
    float2* data = g_F + (size_t)vol * N_VOX + (size_t)z * 65536 + tile * 16;

    float2 v[16];
#pragma unroll
    for (int i = 0; i < 16; i++)
        v[i] = data[(size_t)(t + 16*i) * 256 + c];
    fft16(v);
    __syncthreads();
#pragma unroll
    for (int k2 = 1; k2 < 16; k2++)
        v[k2] = cmulf(v[k2], tws[t * k2]);
#pragma unroll
    for (int k2 = 0; k2 < 16; k2++)
        sh[t][k2][c] = v[k2];
    __syncthreads();
    float2 u[16];
#pragma unroll
    for (int n1 = 0; n1 < 16; n1++)
        u[n1] = sh[n1][t][c];
    fft16(u);
#pragma unroll
    for (int k1 = 0; k1 < 16; k1++)
        data[(size_t)(t + 16*k1) * 256 + c] = u[k1];
}

// ---------------------------------------------------------------------------
// Pass 3 fused: z-FFT for X and Y of one batch + shell binning.
// Block = (batch, y, x-tile). Never writes F back.
// ---------------------------------------------------------------------------
__global__ void __launch_bounds__(256, 2)
fft_z_reduce_kernel() {
    __shared__ float2 sh[16][16][16];
    __shared__ float2 tws[256];
    __shared__ float  bins[3 * NUM_SHELLS];
    int tid = threadIdx.x;
    tws[tid] = g_tw[tid];
    for (int i = tid; i < 3 * NUM_SHELLS; i += 256) bins[i] = 0.0f;

    int c = tid & 15;
    int t = tid >> 4;
    int b     = blockIdx.x;
    int batch = b >> 12;
    int rem   = b & 4095;
    int y     = rem >> 4;
    int tile  = rem & 15;
    float2* dX = g_F + (size_t)batch * N_VOX       + (size_t)y * 256 + tile * 16;
    float2* dY = g_F + (size_t)(batch + 2) * N_VOX + (size_t)y * 256 + tile * 16;

    // ---- X volume z-FFT ----
    float2 v[16];
#pragma unroll
    for (int i = 0; i < 16; i++)
        v[i] = dX[(size_t)(t + 16*i) * 65536 + c];
    fft16(v);
    __syncthreads();   // tws + bins init complete
#pragma unroll
    for (int k2 = 1; k2 < 16; k2++)
        v[k2] = cmulf(v[k2], tws[t * k2]);
#pragma unroll
    for (int k2 = 0; k2 < 16; k2++)
        sh[t][k2][c] = v[k2];
    __syncthreads();
    float2 A[16];
#pragma unroll
    for (int n1 = 0; n1 < 16; n1++)
        A[n1] = sh[n1][t][c];
    fft16(A);          // A[k1] = Fx at z = t + 16*k1
    __syncthreads();   // done reading sh; reuse for Y

    // ---- Y volume z-FFT ----
#pragma unroll
    for (int i = 0; i < 16; i++)
        v[i] = dY[(size_t)(t + 16*i) * 65536 + c];
    fft16(v);
#pragma unroll
    for (int k2 = 1; k2 < 16; k2++)
        v[k2] = cmulf(v[k2], tws[t * k2]);
#pragma unroll
    for (int k2 = 0; k2 < 16; k2++)
        sh[t][k2][c] = v[k2];
    __syncthreads();
    float2 Bv[16];
#pragma unroll
    for (int n1 = 0; n1 < 16; n1++)
        Bv[n1] = sh[n1][t][c];
    fft16(Bv);         // Bv[k1] = Fy at z = t + 16*k1

    // ---- bin {num, px, py} ----
    int x  = tile * 16 + c;
    int fx = (x < 128) ? x : x - 256;
    int fy = (y < 128) ? y : y - 256;
    int rxy = fx*fx + fy*fy;
#pragma unroll
    for (int k1 = 0; k1 < 16; k1++) {
        int z  = t + 16*k1;
        int fz = (z < 128) ? z : z - 256;
        int bin = (int)sqrtf((float)(rxy + fz*fz));
        float2 a = A[k1], bb = Bv[k1];
        atomicAdd(&bins[bin],                  a.x*bb.x + a.y*bb.y);
        atomicAdd(&bins[NUM_SHELLS   + bin],   a.x*a.x + a.y*a.y);
        atomicAdd(&bins[2*NUM_SHELLS + bin],   bb.x*bb.x + bb.y*bb.y);
    }
    __syncthreads();
    float* acc = g_acc + batch * 3 * NUM_SHELLS;
    for (int i = tid; i < 3 * NUM_SHELLS; i += 256)
        atomicAdd(&acc[i], bins[i]);
}

// ---------------------------------------------------------------------------
__global__ void final_kernel(float* __restrict__ out) {
    __shared__ float red[256];
    int tid = threadIdx.x;
    float s = 0.0f;
    for (int i = tid; i < 2 * NUM_SHELLS; i += 256) {
        int bt = i / NUM_SHELLS;
        int sh_ = i % NUM_SHELLS;
        const float* acc = g_acc + bt * 3 * NUM_SHELLS;
        float num = acc[sh_];
        float px  = acc[NUM_SHELLS + sh_];
        float py  = acc[2*NUM_SHELLS + sh_];
        s += num / sqrtf(px * py + 1e-8f);
    }
    red[tid] = s;
    __syncthreads();
    for (int o = 128; o > 0; o >>= 1) {
        if (tid < o) red[tid] += red[tid + o];
        __syncthreads();
    }
    if (tid == 0) out[0] = red[0] / (2.0f * NUM_SHELLS);
}

// ---------------------------------------------------------------------------
extern "C" void kernel_launch(void* const* d_in, const int* in_sizes, int n_in,
                              void* d_out, int out_size) {
    const float* X = (const float*)d_in[0];
    const float* Y = (const float*)d_in[1];

    init_kernel<<<1, 256>>>();
    fft_x_kernel<<<16384, 256>>>(X, Y);     // 4 vols * 65536 lines / 16
    fft_y_kernel<<<16384, 256>>>();         // 4 vols * 256 z * 16 tiles
    fft_z_reduce_kernel<<<8192, 256>>>();   // 2 batches * 256 y * 16 tiles
    final_kernel<<<1, 256>>>((float*)d_out);
}

// round 7
// speedup vs baseline: 1.7279x; 1.0057x over previous
#include <cuda_runtime.h>
#include <math.h>

#define N_VOX (256*256*256)
#define NUM_SHELLS 222
#define NB (2*3*NUM_SHELLS)

// Scratch: 4 complex volumes, two buffers (ping-pong with axis transpose).
// g_F : [vol][z][y][x]   (after pass 1)
// g_F2: [vol][y][z][x]   (after pass 2, z becomes the stride-256 axis)
__device__ float2 g_F [(size_t)4 * N_VOX];
__device__ float2 g_F2[(size_t)4 * N_VOX];
__device__ float  g_acc[NB];
__device__ float2 g_tw[256];   // W256^k

__constant__ float2 TW16C[8] = {
    { 1.0f,           0.0f          },
    { 0.92387953251f, -0.38268343236f },
    { 0.70710678119f, -0.70710678119f },
    { 0.38268343236f, -0.92387953251f },
    { 0.0f,          -1.0f          },
    {-0.38268343236f, -0.92387953251f },
    {-0.70710678119f, -0.70710678119f },
    {-0.92387953251f, -0.38268343236f }
};

__device__ __forceinline__ float2 cmulf(float2 a, float2 b) {
    return make_float2(a.x*b.x - a.y*b.y, a.x*b.y + a.y*b.x);
}

// 16-point radix-2 DIT FFT, fully in registers. Natural in -> natural out.
__device__ __forceinline__ void fft16(float2 v[16]) {
    float2 t;
#define SWP(a,b) { t = v[a]; v[a] = v[b]; v[b] = t; }
    SWP(1,8) SWP(2,4) SWP(3,12) SWP(5,10) SWP(7,14) SWP(11,13)
#undef SWP
#pragma unroll
    for (int st = 0; st < 4; st++) {
        int half = 1 << st;
#pragma unroll
        for (int j = 0; j < 8; j++) {
            int pos = j & (half - 1);
            int i0  = ((j >> st) << (st + 1)) + pos;
            int i1  = i0 + half;
            float2 w = TW16C[pos << (3 - st)];
            float2 b = cmulf(w, v[i1]);
            float2 a = v[i0];
            v[i0] = make_float2(a.x + b.x, a.y + b.y);
            v[i1] = make_float2(a.x - b.x, a.y - b.y);
        }
    }
}

// ---------------------------------------------------------------------------
__global__ void init_kernel() {
    int tid = threadIdx.x;
    for (int i = tid; i < NB; i += blockDim.x) g_acc[i] = 0.0f;
    if (tid < 256) {
        float ang = -6.283185307179586f * (float)tid / 256.0f;
        float s, c;
        sincosf(ang, &s, &c);
        g_tw[tid] = make_float2(c, s);
    }
}

// ---------------------------------------------------------------------------
// Pass 1: x-FFT (contiguous), real -> complex into g_F [vol][z][y][x].
// ---------------------------------------------------------------------------
__global__ void __launch_bounds__(256)
fft_x_kernel(const float* __restrict__ X, const float* __restrict__ Y) {
    __shared__ float2 sh[16][16][17];
    __shared__ float2 tws[256];
    int tid = threadIdx.x;
    tws[tid] = g_tw[tid];
    int tt = tid & 15;
    int l  = tid >> 4;
    int line = blockIdx.x * 16 + l;
    int vol  = line >> 16;
    int lin  = line & 65535;
    const float* src = (vol < 2) ? (X + (size_t)vol * N_VOX)
                                 : (Y + (size_t)(vol - 2) * N_VOX);
    size_t base = (size_t)lin * 256;

    float2 v[16];
#pragma unroll
    for (int i = 0; i < 16; i++)
        v[i] = make_float2(src[base + tt + 16*i], 0.0f);
    fft16(v);
    __syncthreads();
#pragma unroll
    for (int k2 = 1; k2 < 16; k2++)
        v[k2] = cmulf(v[k2], tws[tt * k2]);
#pragma unroll
    for (int k2 = 0; k2 < 16; k2++)
        sh[l][tt][k2] = v[k2];
    __syncthreads();
    float2 u[16];
#pragma unroll
    for (int n1 = 0; n1 < 16; n1++)
        u[n1] = sh[l][n1][tt];
    fft16(u);
    float2* dst = g_F + (size_t)vol * N_VOX + base;
#pragma unroll
    for (int k1 = 0; k1 < 16; k1++)
        dst[tt + 16*k1] = u[k1];
}

// ---------------------------------------------------------------------------
// Pass 2: y-FFT. Reads g_F [vol][z][y][x] (stride-256 over y, fast pattern),
// writes g_F2 [vol][y][z][x] (512KB-strided STORES — fire-and-forget).
// Block = (vol, z, x-tile of 16).
// ---------------------------------------------------------------------------
__global__ void __launch_bounds__(256)
fft_y_kernel() {
    __shared__ float2 sh[16][16][16];
    __shared__ float2 tws[256];
    int tid = threadIdx.x;
    tws[tid] = g_tw[tid];
    int c = tid & 15;
    int t = tid >> 4;
    int b    = blockIdx.x;
    int vol  = b >> 12;
    int rem  = b & 4095;
    int z    = rem >> 4;
    int tile = rem & 15;
    const float2* srcv = g_F  + (size_t)vol * N_VOX + (size_t)z * 65536 + tile * 16;
    float2*       dstv = g_F2 + (size_t)vol * N_VOX + (size_t)z * 256   + tile * 16;

    float2 v[16];
#pragma unroll
    for (int i = 0; i < 16; i++)
        v[i] = srcv[(size_t)(t + 16*i) * 256 + c];
    fft16(v);
    __syncthreads();
#pragma unroll
    for (int k2 = 1; k2 < 16; k2++)
        v[k2] = cmulf(v[k2], tws[t * k2]);
#pragma unroll
    for (int k2 = 0; k2 < 16; k2++)
        sh[t][k2][c] = v[k2];
    __syncthreads();
    float2 u[16];
#pragma unroll
    for (int n1 = 0; n1 < 16; n1++)
        u[n1] = sh[n1][t][c];
    fft16(u);
    // u[k1] is y = t + 16*k1; write to [y][z][x] layout
#pragma unroll
    for (int k1 = 0; k1 < 16; k1++)
        dstv[(size_t)(t + 16*k1) * 65536 + c] = u[k1];
}

// ---------------------------------------------------------------------------
// Pass 3 fused: z-FFT (X and Y of one batch) + shell binning.
// Reads g_F2 [vol][y][z][x]: z is now the stride-256 axis -> fast loads.
// Block = (batch, y, x-tile). Never writes F back.
// ---------------------------------------------------------------------------
__global__ void __launch_bounds__(256, 2)
fft_z_reduce_kernel() {
    __shared__ float2 sh[16][16][16];
    __shared__ float2 tws[256];
    __shared__ float  bins[3 * NUM_SHELLS];
    int tid = threadIdx.x;
    tws[tid] = g_tw[tid];
    for (int i = tid; i < 3 * NUM_SHELLS; i += 256) bins[i] = 0.0f;

    int c = tid & 15;
    int t = tid >> 4;
    int b     = blockIdx.x;
    int batch = b >> 12;
    int rem   = b & 4095;
    int y     = rem >> 4;
    int tile  = rem & 15;
    const float2* dX = g_F2 + (size_t)batch * N_VOX       + (size_t)y * 65536 + tile * 16;
    const float2* dY = g_F2 + (size_t)(batch + 2) * N_VOX + (size_t)y * 65536 + tile * 16;

    // ---- X volume z-FFT ----
    float2 v[16];
#pragma unroll
    for (int i = 0; i < 16; i++)
        v[i] = dX[(size_t)(t + 16*i) * 256 + c];
    fft16(v);
    __syncthreads();   // tws + bins init complete
#pragma unroll
    for (int k2 = 1; k2 < 16; k2++)
        v[k2] = cmulf(v[k2], tws[t * k2]);
#pragma unroll
    for (int k2 = 0; k2 < 16; k2++)
        sh[t][k2][c] = v[k2];
    __syncthreads();
    float2 A[16];
#pragma unroll
    for (int n1 = 0; n1 < 16; n1++)
        A[n1] = sh[n1][t][c];
    fft16(A);          // A[k1] = Fx at z = t + 16*k1
    __syncthreads();   // done reading sh; reuse for Y

    // ---- Y volume z-FFT ----
#pragma unroll
    for (int i = 0; i < 16; i++)
        v[i] = dY[(size_t)(t + 16*i) * 256 + c];
    fft16(v);
#pragma unroll
    for (int k2 = 1; k2 < 16; k2++)
        v[k2] = cmulf(v[k2], tws[t * k2]);
#pragma unroll
    for (int k2 = 0; k2 < 16; k2++)
        sh[t][k2][c] = v[k2];
    __syncthreads();
    float2 Bv[16];
#pragma unroll
    for (int n1 = 0; n1 < 16; n1++)
        Bv[n1] = sh[n1][t][c];
    fft16(Bv);         // Bv[k1] = Fy at z = t + 16*k1

    // ---- bin {num, px, py} ----
    int x  = tile * 16 + c;
    int fx = (x < 128) ? x : x - 256;
    int fy = (y < 128) ? y : y - 256;
    int rxy = fx*fx + fy*fy;
#pragma unroll
    for (int k1 = 0; k1 < 16; k1++) {
        int z  = t + 16*k1;
        int fz = (z < 128) ? z : z - 256;
        int bin = (int)sqrtf((float)(rxy + fz*fz));
        float2 a = A[k1], bb = Bv[k1];
        atomicAdd(&bins[bin],                  a.x*bb.x + a.y*bb.y);
        atomicAdd(&bins[NUM_SHELLS   + bin],   a.x*a.x + a.y*a.y);
        atomicAdd(&bins[2*NUM_SHELLS + bin],   bb.x*bb.x + bb.y*bb.y);
    }
    __syncthreads();
    float* acc = g_acc + batch * 3 * NUM_SHELLS;
    for (int i = tid; i < 3 * NUM_SHELLS; i += 256)
        atomicAdd(&acc[i], bins[i]);
}

// ---------------------------------------------------------------------------
__global__ void final_kernel(float* __restrict__ out) {
    __shared__ float red[256];
    int tid = threadIdx.x;
    float s = 0.0f;
    for (int i = tid; i < 2 * NUM_SHELLS; i += 256) {
        int bt = i / NUM_SHELLS;
        int sh_ = i % NUM_SHELLS;
        const float* acc = g_acc + bt * 3 * NUM_SHELLS;
        float num = acc[sh_];
        float px  = acc[NUM_SHELLS + sh_];
        float py  = acc[2*NUM_SHELLS + sh_];
        s += num / sqrtf(px * py + 1e-8f);
    }
    red[tid] = s;
    __syncthreads();
    for (int o = 128; o > 0; o >>= 1) {
        if (tid < o) red[tid] += red[tid + o];
        __syncthreads();
    }
    if (tid == 0) out[0] = red[0] / (2.0f * NUM_SHELLS);
}

// ---------------------------------------------------------------------------
extern "C" void kernel_launch(void* const* d_in, const int* in_sizes, int n_in,
                              void* d_out, int out_size) {
    const float* X = (const float*)d_in[0];
    const float* Y = (const float*)d_in[1];

    init_kernel<<<1, 256>>>();
    fft_x_kernel<<<16384, 256>>>(X, Y);     // 4 vols * 65536 lines / 16
    fft_y_kernel<<<16384, 256>>>();         // 4 vols * 256 z * 16 tiles
    fft_z_reduce_kernel<<<8192, 256>>>();   // 2 batches * 256 y * 16 tiles
    final_kernel<<<1, 256>>>((float*)d_out);
}

// round 8
// speedup vs baseline: 4.7125x; 2.7273x over previous
#include <cuda_runtime.h>
#include <math.h>

#define N_VOX (256*256*256)
#define NUM_SHELLS 222
#define NB (2*3*NUM_SHELLS)

// Hermitian-packed: 2 complex volumes (Z = X + iY per batch), two buffers.
// g_F : [batch][z][y][x]   (after pass 1)
// g_F2: [batch][y][z][x]   (after pass 2; z becomes the stride-256 axis)
__device__ float2 g_F [(size_t)2 * N_VOX];
__device__ float2 g_F2[(size_t)2 * N_VOX];
__device__ float  g_acc[NB];
__device__ float2 g_tw[256];   // W256^k

__constant__ float2 TW16C[8] = {
    { 1.0f,           0.0f          },
    { 0.92387953251f, -0.38268343236f },
    { 0.70710678119f, -0.70710678119f },
    { 0.38268343236f, -0.92387953251f },
    { 0.0f,          -1.0f          },
    {-0.38268343236f, -0.92387953251f },
    {-0.70710678119f, -0.70710678119f },
    {-0.92387953251f, -0.38268343236f }
};

__device__ __forceinline__ float2 cmulf(float2 a, float2 b) {
    return make_float2(a.x*b.x - a.y*b.y, a.x*b.y + a.y*b.x);
}

// 16-point radix-2 DIT FFT in registers. Natural in -> natural out.
__device__ __forceinline__ void fft16(float2 v[16]) {
    float2 t;
#define SWP(a,b) { t = v[a]; v[a] = v[b]; v[b] = t; }
    SWP(1,8) SWP(2,4) SWP(3,12) SWP(5,10) SWP(7,14) SWP(11,13)
#undef SWP
#pragma unroll
    for (int st = 0; st < 4; st++) {
        int half = 1 << st;
#pragma unroll
        for (int j = 0; j < 8; j++) {
            int pos = j & (half - 1);
            int i0  = ((j >> st) << (st + 1)) + pos;
            int i1  = i0 + half;
            float2 w = TW16C[pos << (3 - st)];
            float2 b = cmulf(w, v[i1]);
            float2 a = v[i0];
            v[i0] = make_float2(a.x + b.x, a.y + b.y);
            v[i1] = make_float2(a.x - b.x, a.y - b.y);
        }
    }
}

// ---------------------------------------------------------------------------
__global__ void init_kernel() {
    int tid = threadIdx.x;
    for (int i = tid; i < NB; i += blockDim.x) g_acc[i] = 0.0f;
    if (tid < 256) {
        float ang = -6.283185307179586f * (float)tid / 256.0f;
        float s, c;
        sincosf(ang, &s, &c);
        g_tw[tid] = make_float2(c, s);
    }
}

// ---------------------------------------------------------------------------
// Pass 1: x-FFT of Z = X + iY (one complex volume per batch).
// 16 lines/block, 16 threads/line. Writes g_F [batch][z][y][x].
// ---------------------------------------------------------------------------
__global__ void __launch_bounds__(256)
fft_x_kernel(const float* __restrict__ X, const float* __restrict__ Y) {
    __shared__ float2 sh[16][16][17];
    __shared__ float2 tws[256];
    int tid = threadIdx.x;
    tws[tid] = g_tw[tid];
    int tt = tid & 15;
    int l  = tid >> 4;
    int line = blockIdx.x * 16 + l;       // 0 .. 131071
    int vol  = line >> 16;                // batch 0/1
    int lin  = line & 65535;
    const float* sx = X + (size_t)vol * N_VOX + (size_t)lin * 256;
    const float* sy = Y + (size_t)vol * N_VOX + (size_t)lin * 256;

    float2 v[16];
#pragma unroll
    for (int i = 0; i < 16; i++)
        v[i] = make_float2(sx[tt + 16*i], sy[tt + 16*i]);
    fft16(v);
    __syncthreads();
#pragma unroll
    for (int k2 = 1; k2 < 16; k2++)
        v[k2] = cmulf(v[k2], tws[tt * k2]);
#pragma unroll
    for (int k2 = 0; k2 < 16; k2++)
        sh[l][tt][k2] = v[k2];
    __syncthreads();
    float2 u[16];
#pragma unroll
    for (int n1 = 0; n1 < 16; n1++)
        u[n1] = sh[l][n1][tt];
    fft16(u);
    float2* dst = g_F + (size_t)vol * N_VOX + (size_t)lin * 256;
#pragma unroll
    for (int k1 = 0; k1 < 16; k1++)
        dst[tt + 16*k1] = u[k1];
}

// ---------------------------------------------------------------------------
// Pass 2: y-FFT. Reads g_F [b][z][y][x] (stride-256 loads),
// writes g_F2 [b][y][z][x] (strided stores, fire-and-forget).
// ---------------------------------------------------------------------------
__global__ void __launch_bounds__(256)
fft_y_kernel() {
    __shared__ float2 sh[16][16][16];
    __shared__ float2 tws[256];
    int tid = threadIdx.x;
    tws[tid] = g_tw[tid];
    int c = tid & 15;
    int t = tid >> 4;
    int b    = blockIdx.x;
    int vol  = b >> 12;                  // batch 0/1
    int rem  = b & 4095;
    int z    = rem >> 4;
    int tile = rem & 15;
    const float2* srcv = g_F  + (size_t)vol * N_VOX + (size_t)z * 65536 + tile * 16;
    float2*       dstv = g_F2 + (size_t)vol * N_VOX + (size_t)z * 256   + tile * 16;

    float2 v[16];
#pragma unroll
    for (int i = 0; i < 16; i++)
        v[i] = srcv[(size_t)(t + 16*i) * 256 + c];
    fft16(v);
    __syncthreads();
#pragma unroll
    for (int k2 = 1; k2 < 16; k2++)
        v[k2] = cmulf(v[k2], tws[t * k2]);
#pragma unroll
    for (int k2 = 0; k2 < 16; k2++)
        sh[t][k2][c] = v[k2];
    __syncthreads();
    float2 u[16];
#pragma unroll
    for (int n1 = 0; n1 < 16; n1++)
        u[n1] = sh[n1][t][c];
    fft16(u);
#pragma unroll
    for (int k1 = 0; k1 < 16; k1++)
        dstv[(size_t)(t + 16*k1) * 65536 + c] = u[k1];
}

// ---------------------------------------------------------------------------
// Pass 3: z-FFT of direct + mirrored columns, Hermitian unpack (Fx,Fy from
// Fz(k), Fz(-k)), shell binning with warp run-aggregation.
// Canonical y = 0..128; per-voxel weights cover the mirror half.
// Block = (batch, y, x-tile of 16). 2*129*16 = 4128 blocks.
// ---------------------------------------------------------------------------
__global__ void __launch_bounds__(256, 2)
fft_z_reduce_kernel() {
    __shared__ float2 sh[4096];          // 16x16x16 transpose / mirror exchange
    __shared__ float2 tws[256];
    __shared__ float  bins[3 * NUM_SHELLS];
    int tid = threadIdx.x;
    tws[tid] = g_tw[tid];
    for (int i = tid; i < 3 * NUM_SHELLS; i += 256) bins[i] = 0.0f;

    int c = tid & 15;
    int t = tid >> 4;
    int bI    = blockIdx.x;
    int batch = bI / 2064;
    int rem   = bI % 2064;
    int y     = rem >> 4;                // 0..128
    int tile  = rem & 15;
    int x  = tile * 16 + c;
    int xm = (256 - x) & 255;
    int ym = (256 - y) & 255;
    const float2* base = g_F2 + (size_t)batch * N_VOX;

    // ---- z-FFT of direct columns (x, y) ----
    float2 v[16];
#pragma unroll
    for (int i = 0; i < 16; i++)
        v[i] = base[(size_t)y * 65536 + (size_t)(t + 16*i) * 256 + x];
    fft16(v);
    __syncthreads();   // tws + bins ready
#pragma unroll
    for (int k2 = 1; k2 < 16; k2++)
        v[k2] = cmulf(v[k2], tws[t * k2]);
#pragma unroll
    for (int k2 = 0; k2 < 16; k2++)
        sh[(t * 16 + k2) * 16 + c] = v[k2];
    __syncthreads();
    float2 A[16];
#pragma unroll
    for (int n1 = 0; n1 < 16; n1++)
        A[n1] = sh[(n1 * 16 + t) * 16 + c];
    fft16(A);                            // A[k1] = Fz(x,y, z=t+16k1)
    __syncthreads();

    // ---- z-FFT of mirrored columns (xm, ym) ----
#pragma unroll
    for (int i = 0; i < 16; i++)
        v[i] = base[(size_t)ym * 65536 + (size_t)(t + 16*i) * 256 + xm];
    fft16(v);
#pragma unroll
    for (int k2 = 1; k2 < 16; k2++)
        v[k2] = cmulf(v[k2], tws[t * k2]);
#pragma unroll
    for (int k2 = 0; k2 < 16; k2++)
        sh[(t * 16 + k2) * 16 + c] = v[k2];
    __syncthreads();
    float2 u[16];
#pragma unroll
    for (int n1 = 0; n1 < 16; n1++)
        u[n1] = sh[(n1 * 16 + t) * 16 + c];
    fft16(u);                            // u[k1] = Fz(xm,ym, z=t+16k1)
    __syncthreads();
    // mirror-exchange layout: sh[z*16 + c] = Fz(xm,ym,z)
#pragma unroll
    for (int k1 = 0; k1 < 16; k1++)
        sh[(t + 16*k1) * 16 + c] = u[k1];
    __syncthreads();

    // ---- unpack + bin ----
    int fx = (x < 128) ? x : x - 256;
    int fy = (y < 128) ? y : y - 256;
    int rxy = fx*fx + fy*fy;
    // weight category: 0 -> always 2; 1 -> depends on z; 2 -> always 0
    bool y_mid  = (unsigned)(y - 1) < 127u;
    bool x_mid  = (unsigned)(x - 1) < 127u;
    bool x_self = (x == 0) || (x == 128);
    int cat = (y_mid || x_mid) ? 0 : (x_self ? 1 : 2);

    const unsigned FULL = 0xffffffffu;
    int lpos = tid & 15;                 // position within 16-lane segment

#pragma unroll
    for (int k1 = 0; k1 < 16; k1++) {
        int z  = t + 16*k1;
        int zm = (256 - z) & 255;
        float2 P = A[k1];                          // Fz(k)
        float2 Q = sh[zm * 16 + c];                // Fz(-k)
        // unscaled unpack (global x4 factor cancels in FSC ratio)
        float Fxr = P.x + Q.x, Fxi = P.y - Q.y;    // 2*Fx
        float Fyr = P.y + Q.y, Fyi = Q.x - P.x;    // 2*Fy
        float fw;
        if (cat == 0) fw = 2.0f;
        else if (cat == 2) fw = 0.0f;
        else {
            bool z_mid  = (unsigned)(z - 1) < 127u;
            bool z_self = (z == 0) || (z == 128);
            fw = z_mid ? 2.0f : (z_self ? 1.0f : 0.0f);
        }
        int fz = (z < 128) ? z : z - 256;
        int bin = (int)sqrtf((float)(rxy + fz*fz));
        float nn = fw * (Fxr*Fyr + Fxi*Fyi);
        float pp = fw * (Fxr*Fxr + Fxi*Fxi);
        float qq = fw * (Fyr*Fyr + Fyi*Fyi);

        // run-aggregation within each 16-lane segment (bin monotone in lpos)
#pragma unroll
        for (int off = 1; off < 16; off <<= 1) {
            int   ob = __shfl_down_sync(FULL, bin, off);
            float on = __shfl_down_sync(FULL, nn,  off);
            float op = __shfl_down_sync(FULL, pp,  off);
            float oq = __shfl_down_sync(FULL, qq,  off);
            if (lpos + off < 16 && ob == bin) { nn += on; pp += op; qq += oq; }
        }
        int pb = __shfl_up_sync(FULL, bin, 1);
        if (lpos == 0 || pb != bin) {
            atomicAdd(&bins[bin],                nn);
            atomicAdd(&bins[NUM_SHELLS   + bin], pp);
            atomicAdd(&bins[2*NUM_SHELLS + bin], qq);
        }
    }
    __syncthreads();
    float* acc = g_acc + batch * 3 * NUM_SHELLS;
    for (int i = tid; i < 3 * NUM_SHELLS; i += 256)
        atomicAdd(&acc[i], bins[i]);
}

// ---------------------------------------------------------------------------
__global__ void final_kernel(float* __restrict__ out) {
    __shared__ float red[256];
    int tid = threadIdx.x;
    float s = 0.0f;
    for (int i = tid; i < 2 * NUM_SHELLS; i += 256) {
        int bt = i / NUM_SHELLS;
        int sh_ = i % NUM_SHELLS;
        const float* acc = g_acc + bt * 3 * NUM_SHELLS;
        float num = acc[sh_];
        float px  = acc[NUM_SHELLS + sh_];
        float py  = acc[2*NUM_SHELLS + sh_];
        s += num / sqrtf(px * py + 1e-8f);
    }
    red[tid] = s;
    __syncthreads();
    for (int o = 128; o > 0; o >>= 1) {
        if (tid < o) red[tid] += red[tid + o];
        __syncthreads();
    }
    if (tid == 0) out[0] = red[0] / (2.0f * NUM_SHELLS);
}

// ---------------------------------------------------------------------------
extern "C" void kernel_launch(void* const* d_in, const int* in_sizes, int n_in,
                              void* d_out, int out_size) {
    const float* X = (const float*)d_in[0];
    const float* Y = (const float*)d_in[1];

    init_kernel<<<1, 256>>>();
    fft_x_kernel<<<8192, 256>>>(X, Y);      // 2 packed vols * 65536 lines / 16
    fft_y_kernel<<<8192, 256>>>();          // 2 vols * 256 z * 16 tiles
    fft_z_reduce_kernel<<<4128, 256>>>();   // 2 batches * 129 y * 16 tiles
    final_kernel<<<1, 256>>>((float*)d_out);
}